// round 9
// baseline (speedup 1.0000x reference)
#include <cuda_runtime.h>

#define NN 2048
#define NTHR 1024
#define NBLK 148
#define EPSC 1e-10f
#define ITERS 50

// ---------------- device scratch (static, per harness rules) ---------------
__device__ float g_s[NN];      // scores sorted descending
__device__ float g_labs[NN];   // labels permuted by score-rank
__device__ float g_part0[NN];  // idcg partials
__device__ unsigned g_arrive = 0;
__device__ unsigned g_gen = 0;

// ---------------- scoped ops (no CCTL.IVALL — preserve caches) -------------
__device__ __forceinline__ unsigned ld_acq(const unsigned* p) {
    unsigned v;
    asm volatile("ld.acquire.gpu.u32 %0, [%1];" : "=r"(v) : "l"(p) : "memory");
    return v;
}
__device__ __forceinline__ void st_rel(unsigned* p, unsigned v) {
    asm volatile("st.release.gpu.u32 [%0], %1;" :: "l"(p), "r"(v) : "memory");
}
__device__ __forceinline__ void st_rlx(unsigned* p, unsigned v) {
    asm volatile("st.relaxed.gpu.u32 [%0], %1;" :: "l"(p), "r"(v) : "memory");
}
__device__ __forceinline__ unsigned atom_add_rel(unsigned* p, unsigned v) {
    unsigned o;
    asm volatile("atom.add.release.gpu.u32 %0, [%1], %2;"
                 : "=r"(o) : "l"(p), "r"(v) : "memory");
    return o;
}

// Central grid barrier (R3-proven). Used exactly once.
__device__ __forceinline__ void grid_sync(unsigned& gen) {
    __syncthreads();
    if (threadIdx.x == 0) {
        gen++;
        unsigned prev = atom_add_rel(&g_arrive, 1u);
        if (prev == NBLK - 1) {
            st_rlx(&g_arrive, 0u);
            st_rel(&g_gen, gen);
        } else {
            while (ld_acq(&g_gen) != gen) { }
        }
    }
    __syncthreads();
}

__device__ __forceinline__ float warp_sum(float v) {
    #pragma unroll
    for (int o = 16; o; o >>= 1) v += __shfl_xor_sync(0xffffffffu, v, o);
    return v;
}

// dual scan: forward inclusive on .x, backward inclusive on .y
__device__ __forceinline__ float2 scan_fb(float2 v, int lane) {
    #pragma unroll
    for (int o = 1; o < 32; o <<= 1) {
        float ax = __shfl_up_sync(0xffffffffu, v.x, o);
        float ay = __shfl_down_sync(0xffffffffu, v.y, o);
        if (lane >= o)      v.x += ax;
        if (lane < 32 - o)  v.y += ay;
    }
    return v;
}

struct O2 { float a, b; };

// out = W~ x, W~[k][m] = exp(-|s_k - s_m|), s sorted descending.
// Thread owns k0=2*tid, k1=k0+1; x entirely in registers.
// (W~x)_k = F_k * prefix_k(x/F) + Fi_k * suffix_{k+1}(x*F).
// ONE __syncthreads; sA/sB double-buffered across alternating calls.
__device__ __forceinline__ O2 applyW(
    float x0, float x1,
    float F0, float F1, float Fi0, float Fi1,
    float* sA, float* sB, int lane, int warp)
{
    float z0 = x0 * Fi0, z1 = x1 * Fi1;   // forward-scan component
    float w0 = x0 * F0,  w1 = x1 * F1;    // backward-scan component
    float2 pr = make_float2(z0 + z1, w0 + w1);
    float2 wp = scan_fb(pr, lane);
    if (lane == 31) sA[warp] = wp.x;      // forward warp total
    if (lane == 0)  sB[warp] = wp.y;      // backward warp total
    __syncthreads();
    float2 t  = make_float2(sA[lane], sB[lane]);   // broadcast reads
    float2 ts = scan_fb(t, lane);
    float bx = __shfl_sync(0xffffffffu, ts.x - t.x, warp);  // warps < own
    float by = __shfl_sync(0xffffffffu, ts.y - t.y, warp);  // warps > own
    float exl = wp.x - pr.x;   // lanes < lane (forward exclusive)
    float eyl = wp.y - pr.y;   // lanes > lane (backward exclusive)
    float A0   = bx + exl + z0;   // inclusive prefix of z at k0
    float A1   = A0 + z1;
    float Bk1  = by + eyl + w1;   // inclusive suffix of w at k1
    O2 o;
    o.a = fmaf(F0, A0, Fi0 * Bk1);           // suffix_{k0+1} = Bk1
    o.b = fmaf(F1, A1, Fi1 * (by + eyl));    // suffix_{k1+1}
    return o;
}

__global__ void __launch_bounds__(NTHR, 1)
softndcg_kernel(const float* __restrict__ y_pred,
                const float* __restrict__ y_true,
                float* __restrict__ out)
{
    __shared__ float sA0[32], sB0[32];  // buffer 0
    __shared__ float sA1[32], sB1[32];  // buffer 1
    __shared__ float sred[32];
    __shared__ float s_idcg;

    const int tid  = threadIdx.x;
    const int lane = tid & 31;
    const int warp = tid >> 5;
    const int bid  = blockIdx.x;

    unsigned gen = (tid == 0) ? ld_acq(&g_gen) : 0u;  // replay-safe

    // ---- Setup (all 148 CTAs): ranks + sorted arrays + idcg partials -------
    {
        int r = bid + NBLK * warp;  // warps 0..13 carry rows
        if (r < NN) {
            float ai = __ldg(&y_pred[r]);
            float ti = __ldg(&y_true[r]);
            int ca = 0, cl = 0;
            for (int j = lane; j < NN; j += 32) {
                float aj = __ldg(&y_pred[j]);
                ca += (aj > ai) || (aj == ai && j < r);
                float tj = __ldg(&y_true[j]);  // exp2 monotone: rank on y_true
                cl += (tj > ti) || (tj == ti && j < r);
            }
            #pragma unroll
            for (int o = 16; o; o >>= 1) {
                ca += __shfl_xor_sync(0xffffffffu, ca, o);
                cl += __shfl_xor_sync(0xffffffffu, cl, o);
            }
            if (lane == 0) {
                float lab = exp2f(ti) - 1.0f;
                g_s[ca]    = ai;
                g_labs[ca] = lab;
                g_part0[r] = lab / log2f((float)cl + 2.0f);
            }
        }
    }
    grid_sync(gen);
    if (bid != 0) return;  // only CTA0 runs the O(N) Sinkhorn

    // ---- CTA0: per-thread constants (k0 = 2*tid, k1 = k0+1) ----------------
    const int k0 = 2 * tid, k1 = k0 + 1;
    float s0  = __ldcg(&g_s[k0]), s1 = __ldcg(&g_s[k1]);
    float F0  = expf(s0),  F1  = expf(s1);
    float Fi0 = 1.0f / F0, Fi1 = 1.0f / F1;
    float L0  = __ldcg(&g_labs[k0]), L1 = __ldcg(&g_labs[k1]);

    // idcg reduction (consumed only at the very end, many bars later)
    float p = __ldcg(&g_part0[k0]) + __ldcg(&g_part0[k1]);
    p = warp_sum(p);
    if (lane == 0) sred[warp] = p;
    __syncthreads();
    if (warp == 0) {
        float q = warp_sum(sred[lane]);
        if (lane == 0) s_idcg = q;
    }

    // ---- u0 = 1 / rowsum(W~), v0 = 1  (buffer 0) ---------------------------
    float2 uu, vv = make_float2(1.0f, 1.0f);
    {
        O2 o = applyW(1.f, 1.f, F0, F1, Fi0, Fi1, sA0, sB0, lane, warp);
        uu = make_float2(1.0f / o.a, 1.0f / o.b);
    }

    // ---- Sinkhorn: 50 iterations, registers only ---------------------------
    #pragma unroll 1
    for (int t = 0; t < ITERS; t++) {
        // col step: v <- v / clip(v * (W~ u), EPS)   (buffer 1)
        {
            O2 o = applyW(uu.x, uu.y, F0, F1, Fi0, Fi1, sA1, sB1, lane, warp);
            vv.x = vv.x / fmaxf(vv.x * o.a, EPSC);
            vv.y = vv.y / fmaxf(vv.y * o.b, EPSC);
        }
        // row step: u <- u / clip(u * (W~ v), EPS)   (buffer 0)
        {
            O2 o = applyW(vv.x, vv.y, F0, F1, Fi0, Fi1, sA0, sB0, lane, warp);
            uu.x = uu.x / fmaxf(uu.x * o.a, EPSC);
            uu.y = uu.y / fmaxf(uu.y * o.b, EPSC);
        }
    }

    // ---- Final: dcg = sum_k u_k * (W~ (v .* labs))_k / disc_k  (buffer 1) --
    {
        O2 o = applyW(vv.x * L0, vv.y * L1, F0, F1, Fi0, Fi1,
                      sA1, sB1, lane, warp);
        float d = uu.x * o.a / log2f((float)k0 + 2.0f)
                + uu.y * o.b / log2f((float)k1 + 2.0f);
        d = warp_sum(d);
        if (lane == 0) sred[warp] = d;
        __syncthreads();
        if (warp == 0) {
            float q = warp_sum(sred[lane]);
            if (lane == 0) out[0] = 1.0f - q / s_idcg;
        }
    }
}

extern "C" void kernel_launch(void* const* d_in, const int* in_sizes, int n_in,
                              void* d_out, int out_size) {
    const float* y_pred = (const float*)d_in[0];
    const float* y_true = (const float*)d_in[1];
    float* out = (float*)d_out;
    (void)in_sizes; (void)n_in; (void)out_size;
    softndcg_kernel<<<NBLK, NTHR>>>(y_pred, y_true, out);
}

// round 10
// speedup vs baseline: 1.4868x; 1.4868x over previous
#include <cuda_runtime.h>

#define NN 2048
#define NTHR 512       // launch width (setup needs 14 warps)
#define LOOPT 256      // Sinkhorn threads (CTA0 only)
#define LWARPS (LOOPT / 32)
#define EPB 8          // elements per thread (LOOPT*EPB == NN)
#define NBLK 148
#define EPSC 1e-10f
#define ITERS 50

// ---------------- device scratch (static, per harness rules) ---------------
__device__ float g_s[NN];      // scores sorted descending
__device__ float g_labs[NN];   // labels permuted by score-rank
__device__ float g_part0[NN];  // idcg partials
__device__ unsigned g_arrive = 0;
__device__ unsigned g_gen = 0;

// ---------------- scoped ops (no CCTL.IVALL — preserve caches) -------------
__device__ __forceinline__ unsigned ld_acq(const unsigned* p) {
    unsigned v;
    asm volatile("ld.acquire.gpu.u32 %0, [%1];" : "=r"(v) : "l"(p) : "memory");
    return v;
}
__device__ __forceinline__ void st_rel(unsigned* p, unsigned v) {
    asm volatile("st.release.gpu.u32 [%0], %1;" :: "l"(p), "r"(v) : "memory");
}
__device__ __forceinline__ void st_rlx(unsigned* p, unsigned v) {
    asm volatile("st.relaxed.gpu.u32 [%0], %1;" :: "l"(p), "r"(v) : "memory");
}
__device__ __forceinline__ unsigned atom_add_rel(unsigned* p, unsigned v) {
    unsigned o;
    asm volatile("atom.add.release.gpu.u32 %0, [%1], %2;"
                 : "=r"(o) : "l"(p), "r"(v) : "memory");
    return o;
}

// Central grid barrier (R3-proven). Used exactly once.
__device__ __forceinline__ void grid_sync(unsigned& gen) {
    __syncthreads();
    if (threadIdx.x == 0) {
        gen++;
        unsigned prev = atom_add_rel(&g_arrive, 1u);
        if (prev == NBLK - 1) {
            st_rlx(&g_arrive, 0u);
            st_rel(&g_gen, gen);
        } else {
            while (ld_acq(&g_gen) != gen) { }
        }
    }
    __syncthreads();
}

__device__ __forceinline__ float warp_sum(float v) {
    #pragma unroll
    for (int o = 16; o; o >>= 1) v += __shfl_xor_sync(0xffffffffu, v, o);
    return v;
}

// dual scan: forward inclusive on .x, backward inclusive on .y
__device__ __forceinline__ float2 scan_fb(float2 v, int lane) {
    #pragma unroll
    for (int o = 1; o < 32; o <<= 1) {
        float ax = __shfl_up_sync(0xffffffffu, v.x, o);
        float ay = __shfl_down_sync(0xffffffffu, v.y, o);
        if (lane >= o)      v.x += ax;
        if (lane < 32 - o)  v.y += ay;
    }
    return v;
}

// out = W~ x, W~[k][m] = exp(-|s_k - s_m|), s sorted descending.
// Thread owns k = tid*EPB .. tid*EPB+7 (contiguous). x in registers.
// (W~x)_k = F_k * prefix_incl_k(x/F) + Fi_k * suffix_excl_k(x*F).
// ONE __syncthreads; sA/sB double-buffered across alternating calls.
__device__ __forceinline__ void applyW8(
    const float* __restrict__ x, const float* __restrict__ F,
    const float* __restrict__ Fi, float* __restrict__ out,
    float* sA, float* sB, int lane, int warp)
{
    float z[EPB], w[EPB], pz[EPB], sw[EPB];
    #pragma unroll
    for (int e = 0; e < EPB; e++) { z[e] = x[e] * Fi[e]; w[e] = x[e] * F[e]; }
    pz[0] = z[0];
    #pragma unroll
    for (int e = 1; e < EPB; e++) pz[e] = pz[e - 1] + z[e];   // local prefix
    sw[EPB - 1] = w[EPB - 1];
    #pragma unroll
    for (int e = EPB - 2; e >= 0; e--) sw[e] = sw[e + 1] + w[e];  // local suffix

    float2 wp = scan_fb(make_float2(pz[EPB - 1], sw[0]), lane);
    if (lane == 31) sA[warp] = wp.x;   // warp z-total (inclusive fwd @31)
    if (lane == 0)  sB[warp] = wp.y;   // warp w-total (inclusive bwd @0)
    __syncthreads();
    float bz = 0.f, bw = 0.f;
    #pragma unroll
    for (int q = 0; q < LWARPS; q++) {   // serial combine, smem broadcast reads
        float a = sA[q], b = sB[q];
        if (q < warp) bz += a;
        if (q > warp) bw += b;
    }
    float exz = bz + (wp.x - pz[EPB - 1]);  // exclusive fwd base for this thread
    float exw = bw + (wp.y - sw[0]);        // exclusive bwd base for this thread
    #pragma unroll
    for (int e = 0; e < EPB; e++) {
        float A = exz + pz[e];              // inclusive prefix at k
        float S = exw + (sw[e] - w[e]);     // exclusive suffix at k
        out[e] = fmaf(F[e], A, Fi[e] * S);
    }
}

__global__ void __launch_bounds__(NTHR, 1)
softndcg_kernel(const float* __restrict__ y_pred,
                const float* __restrict__ y_true,
                float* __restrict__ out)
{
    __shared__ float sA0[LWARPS], sB0[LWARPS];  // buffer 0
    __shared__ float sA1[LWARPS], sB1[LWARPS];  // buffer 1
    __shared__ float sred[LWARPS];
    __shared__ float s_idcg;

    const int tid  = threadIdx.x;
    const int lane = tid & 31;
    const int warp = tid >> 5;
    const int bid  = blockIdx.x;

    unsigned gen = (tid == 0) ? ld_acq(&g_gen) : 0u;  // replay-safe

    // ---- Setup (all 148 CTAs): ranks + sorted arrays + idcg partials -------
    {
        int r = bid + NBLK * warp;  // warps 0..13 carry rows
        if (r < NN) {
            float ai = __ldg(&y_pred[r]);
            float ti = __ldg(&y_true[r]);
            int ca = 0, cl = 0;
            for (int j = lane; j < NN; j += 32) {
                float aj = __ldg(&y_pred[j]);
                ca += (aj > ai) || (aj == ai && j < r);
                float tj = __ldg(&y_true[j]);  // exp2 monotone: rank on y_true
                cl += (tj > ti) || (tj == ti && j < r);
            }
            #pragma unroll
            for (int o = 16; o; o >>= 1) {
                ca += __shfl_xor_sync(0xffffffffu, ca, o);
                cl += __shfl_xor_sync(0xffffffffu, cl, o);
            }
            if (lane == 0) {
                float lab = exp2f(ti) - 1.0f;
                g_s[ca]    = ai;
                g_labs[ca] = lab;
                g_part0[r] = lab / log2f((float)cl + 2.0f);
            }
        }
    }
    grid_sync(gen);
    if (bid != 0 || tid >= LOOPT) return;  // CTA0, warps 0..7 run Sinkhorn

    // ---- CTA0: per-thread constants, 8 contiguous elements -----------------
    const int base = tid * EPB;
    float F[EPB], Fi[EPB], L[EPB];
    {
        float4 sa = __ldcg(reinterpret_cast<const float4*>(&g_s[base]));
        float4 sb = __ldcg(reinterpret_cast<const float4*>(&g_s[base + 4]));
        float sv[EPB] = {sa.x, sa.y, sa.z, sa.w, sb.x, sb.y, sb.z, sb.w};
        #pragma unroll
        for (int e = 0; e < EPB; e++) { F[e] = expf(sv[e]); Fi[e] = 1.0f / F[e]; }
        float4 la = __ldcg(reinterpret_cast<const float4*>(&g_labs[base]));
        float4 lb = __ldcg(reinterpret_cast<const float4*>(&g_labs[base + 4]));
        L[0]=la.x; L[1]=la.y; L[2]=la.z; L[3]=la.w;
        L[4]=lb.x; L[5]=lb.y; L[6]=lb.z; L[7]=lb.w;
    }

    // idcg reduction (s_idcg consumed only at the very end)
    {
        float4 pa = __ldcg(reinterpret_cast<const float4*>(&g_part0[base]));
        float4 pb = __ldcg(reinterpret_cast<const float4*>(&g_part0[base + 4]));
        float p = ((pa.x + pa.y) + (pa.z + pa.w)) + ((pb.x + pb.y) + (pb.z + pb.w));
        p = warp_sum(p);
        if (lane == 0) sred[warp] = p;
        __syncthreads();
        if (warp == 0 && lane == 0) {
            float q = 0.f;
            #pragma unroll
            for (int i = 0; i < LWARPS; i++) q += sred[i];
            s_idcg = q;
        }
    }

    // ---- u0 = 1 / rowsum(W~), v0 = 1  (buffer 0) ---------------------------
    float u[EPB], v[EPB], x[EPB], o[EPB];
    #pragma unroll
    for (int e = 0; e < EPB; e++) { x[e] = 1.0f; v[e] = 1.0f; }
    applyW8(x, F, Fi, o, sA0, sB0, lane, warp);
    #pragma unroll
    for (int e = 0; e < EPB; e++) u[e] = 1.0f / o[e];

    // ---- Sinkhorn: 50 iterations, registers only ---------------------------
    #pragma unroll 1
    for (int t = 0; t < ITERS; t++) {
        // col step: v <- v / clip(v * (W~ u), EPS)   (buffer 1)
        applyW8(u, F, Fi, o, sA1, sB1, lane, warp);
        #pragma unroll
        for (int e = 0; e < EPB; e++)
            v[e] = __fdividef(v[e], fmaxf(v[e] * o[e], EPSC));
        // row step: u <- u / clip(u * (W~ v), EPS)   (buffer 0)
        applyW8(v, F, Fi, o, sA0, sB0, lane, warp);
        #pragma unroll
        for (int e = 0; e < EPB; e++)
            u[e] = __fdividef(u[e], fmaxf(u[e] * o[e], EPSC));
    }

    // ---- Final: dcg = sum_k u_k * (W~ (v .* labs))_k / disc_k  (buffer 1) --
    {
        #pragma unroll
        for (int e = 0; e < EPB; e++) x[e] = v[e] * L[e];
        applyW8(x, F, Fi, o, sA1, sB1, lane, warp);
        float d = 0.f;
        #pragma unroll
        for (int e = 0; e < EPB; e++)
            d += u[e] * o[e] / log2f((float)(base + e) + 2.0f);
        d = warp_sum(d);
        if (lane == 0) sred[warp] = d;
        __syncthreads();
        if (warp == 0 && lane == 0) {
            float q = 0.f;
            #pragma unroll
            for (int i = 0; i < LWARPS; i++) q += sred[i];
            out[0] = 1.0f - q / s_idcg;
        }
    }
}

extern "C" void kernel_launch(void* const* d_in, const int* in_sizes, int n_in,
                              void* d_out, int out_size) {
    const float* y_pred = (const float*)d_in[0];
    const float* y_true = (const float*)d_in[1];
    float* out = (float*)d_out;
    (void)in_sizes; (void)n_in; (void)out_size;
    softndcg_kernel<<<NBLK, NTHR>>>(y_pred, y_true, out);
}

// round 11
// speedup vs baseline: 3.6728x; 2.4703x over previous
#include <cuda_runtime.h>

#define NN 2048
#define NTHR 512       // launch width (setup needs 14 warps)
#define LOOPT 256      // Sinkhorn threads (CTA0 only)
#define LWARPS (LOOPT / 32)
#define EPB 8          // elements per thread (LOOPT*EPB == NN)
#define NBLK 148
#define EPSC 1e-10f
#define ITERS 50
#define TOLC 1e-6f

// ---------------- device scratch (static, per harness rules) ---------------
__device__ float g_s[NN];      // scores sorted descending
__device__ float g_labs[NN];   // labels permuted by score-rank
__device__ float g_part0[NN];  // idcg partials
__device__ unsigned g_arrive = 0;
__device__ unsigned g_gen = 0;

// ---------------- scoped ops (no CCTL.IVALL — preserve caches) -------------
__device__ __forceinline__ unsigned ld_acq(const unsigned* p) {
    unsigned v;
    asm volatile("ld.acquire.gpu.u32 %0, [%1];" : "=r"(v) : "l"(p) : "memory");
    return v;
}
__device__ __forceinline__ void st_rel(unsigned* p, unsigned v) {
    asm volatile("st.release.gpu.u32 [%0], %1;" :: "l"(p), "r"(v) : "memory");
}
__device__ __forceinline__ void st_rlx(unsigned* p, unsigned v) {
    asm volatile("st.relaxed.gpu.u32 [%0], %1;" :: "l"(p), "r"(v) : "memory");
}
__device__ __forceinline__ unsigned atom_add_rel(unsigned* p, unsigned v) {
    unsigned o;
    asm volatile("atom.add.release.gpu.u32 %0, [%1], %2;"
                 : "=r"(o) : "l"(p), "r"(v) : "memory");
    return o;
}

// Central grid barrier (R3-proven). Used exactly once.
__device__ __forceinline__ void grid_sync(unsigned& gen) {
    __syncthreads();
    if (threadIdx.x == 0) {
        gen++;
        unsigned prev = atom_add_rel(&g_arrive, 1u);
        if (prev == NBLK - 1) {
            st_rlx(&g_arrive, 0u);
            st_rel(&g_gen, gen);
        } else {
            while (ld_acq(&g_gen) != gen) { }
        }
    }
    __syncthreads();
}

__device__ __forceinline__ float warp_sum(float v) {
    #pragma unroll
    for (int o = 16; o; o >>= 1) v += __shfl_xor_sync(0xffffffffu, v, o);
    return v;
}
__device__ __forceinline__ float warp_max(float v) {
    #pragma unroll
    for (int o = 16; o; o >>= 1) v = fmaxf(v, __shfl_xor_sync(0xffffffffu, v, o));
    return v;
}

// dual scan: forward inclusive on .x, backward inclusive on .y
__device__ __forceinline__ float2 scan_fb(float2 v, int lane) {
    #pragma unroll
    for (int o = 1; o < 32; o <<= 1) {
        float ax = __shfl_up_sync(0xffffffffu, v.x, o);
        float ay = __shfl_down_sync(0xffffffffu, v.y, o);
        if (lane >= o)      v.x += ax;
        if (lane < 32 - o)  v.y += ay;
    }
    return v;
}

// out = W~ x, W~[k][m] = exp(-|s_k - s_m|), s sorted descending.
// Thread owns k = tid*EPB .. +7 contiguous; x in registers; ONE bar.
__device__ __forceinline__ void applyW8(
    const float* __restrict__ x, const float* __restrict__ F,
    const float* __restrict__ Fi, float* __restrict__ out,
    float* sA, float* sB, int lane, int warp)
{
    float z[EPB], w[EPB], pz[EPB], sw[EPB];
    #pragma unroll
    for (int e = 0; e < EPB; e++) { z[e] = x[e] * Fi[e]; w[e] = x[e] * F[e]; }
    pz[0] = z[0];
    #pragma unroll
    for (int e = 1; e < EPB; e++) pz[e] = pz[e - 1] + z[e];       // local prefix
    sw[EPB - 1] = w[EPB - 1];
    #pragma unroll
    for (int e = EPB - 2; e >= 0; e--) sw[e] = sw[e + 1] + w[e];  // local suffix

    float2 wp = scan_fb(make_float2(pz[EPB - 1], sw[0]), lane);
    if (lane == 31) sA[warp] = wp.x;
    if (lane == 0)  sB[warp] = wp.y;
    __syncthreads();
    float bz = 0.f, bw = 0.f;
    #pragma unroll
    for (int q = 0; q < LWARPS; q++) {
        float a = sA[q], b = sB[q];
        if (q < warp) bz += a;
        if (q > warp) bw += b;
    }
    float exz = bz + (wp.x - pz[EPB - 1]);
    float exw = bw + (wp.y - sw[0]);
    #pragma unroll
    for (int e = 0; e < EPB; e++) {
        float A = exz + pz[e];             // inclusive prefix at k
        float S = exw + (sw[e] - w[e]);    // exclusive suffix at k
        out[e] = fmaf(F[e], A, Fi[e] * S);
    }
}

__global__ void __launch_bounds__(NTHR, 1)
softndcg_kernel(const float* __restrict__ y_pred,
                const float* __restrict__ y_true,
                float* __restrict__ out)
{
    __shared__ float sA0[LWARPS], sB0[LWARPS];  // scan buffer 0 (row steps)
    __shared__ float sA1[LWARPS], sB1[LWARPS];  // scan buffer 1 (col steps)
    __shared__ float sdev[2][LWARPS];           // convergence, parity-buffered
    __shared__ float sred[LWARPS];
    __shared__ float s_idcg;

    const int tid  = threadIdx.x;
    const int lane = tid & 31;
    const int warp = tid >> 5;
    const int bid  = blockIdx.x;

    unsigned gen = (tid == 0) ? ld_acq(&g_gen) : 0u;  // replay-safe

    // ---- Setup (all 148 CTAs): ranks + sorted arrays + idcg partials -------
    {
        int r = bid + NBLK * warp;  // warps 0..13 carry rows
        if (r < NN) {
            float ai = __ldg(&y_pred[r]);
            float ti = __ldg(&y_true[r]);
            int ca = 0, cl = 0;
            for (int j = lane; j < NN; j += 32) {
                float aj = __ldg(&y_pred[j]);
                ca += (aj > ai) || (aj == ai && j < r);
                float tj = __ldg(&y_true[j]);  // exp2 monotone: rank on y_true
                cl += (tj > ti) || (tj == ti && j < r);
            }
            #pragma unroll
            for (int o = 16; o; o >>= 1) {
                ca += __shfl_xor_sync(0xffffffffu, ca, o);
                cl += __shfl_xor_sync(0xffffffffu, cl, o);
            }
            if (lane == 0) {
                float lab = exp2f(ti) - 1.0f;
                g_s[ca]    = ai;
                g_labs[ca] = lab;
                g_part0[r] = lab / log2f((float)cl + 2.0f);
            }
        }
    }
    grid_sync(gen);
    if (bid != 0 || tid >= LOOPT) return;  // CTA0 warps 0..7 run Sinkhorn

    // ---- CTA0: per-thread constants, 8 contiguous elements -----------------
    const int base = tid * EPB;
    float F[EPB], Fi[EPB], L[EPB];
    {
        float4 sa = __ldcg(reinterpret_cast<const float4*>(&g_s[base]));
        float4 sb = __ldcg(reinterpret_cast<const float4*>(&g_s[base + 4]));
        float sv[EPB] = {sa.x, sa.y, sa.z, sa.w, sb.x, sb.y, sb.z, sb.w};
        #pragma unroll
        for (int e = 0; e < EPB; e++) { F[e] = expf(sv[e]); Fi[e] = 1.0f / F[e]; }
        float4 la = __ldcg(reinterpret_cast<const float4*>(&g_labs[base]));
        float4 lb = __ldcg(reinterpret_cast<const float4*>(&g_labs[base + 4]));
        L[0]=la.x; L[1]=la.y; L[2]=la.z; L[3]=la.w;
        L[4]=lb.x; L[5]=lb.y; L[6]=lb.z; L[7]=lb.w;
    }

    // idcg reduction (s_idcg consumed only at the very end)
    {
        float4 pa = __ldcg(reinterpret_cast<const float4*>(&g_part0[base]));
        float4 pb = __ldcg(reinterpret_cast<const float4*>(&g_part0[base + 4]));
        float p = ((pa.x + pa.y) + (pa.z + pa.w)) + ((pb.x + pb.y) + (pb.z + pb.w));
        p = warp_sum(p);
        if (lane == 0) sred[warp] = p;
        __syncthreads();
        if (warp == 0 && lane == 0) {
            float q = 0.f;
            #pragma unroll
            for (int i = 0; i < LWARPS; i++) q += sred[i];
            s_idcg = q;
        }
    }

    // ---- u0 = 1 / rowsum(W~), v0 = 1  (buffer 0) ---------------------------
    float u[EPB], v[EPB], x[EPB], o[EPB];
    #pragma unroll
    for (int e = 0; e < EPB; e++) { x[e] = 1.0f; v[e] = 1.0f; }
    applyW8(x, F, Fi, o, sA0, sB0, lane, warp);
    #pragma unroll
    for (int e = 0; e < EPB; e++) u[e] = __fdividef(1.0f, o[e]);

    // ---- Sinkhorn: up to 50 iterations, early exit on convergence ----------
    #pragma unroll 1
    for (int t = 0; t < ITERS; t++) {
        const int par = t & 1;
        // col step: colsum = v * (W~ u); dev check piggybacks; v <- 1/o
        applyW8(u, F, Fi, o, sA1, sB1, lane, warp);
        {
            float dv = 0.f;
            #pragma unroll
            for (int e = 0; e < EPB; e++) {
                dv = fmaxf(dv, fabsf(fmaf(v[e], o[e], -1.0f)));
                v[e] = __fdividef(1.0f, o[e]);   // == v/clip(v*o,EPS)
            }
            dv = warp_max(dv);                    // off critical path
            if (lane == 0) sdev[par][warp] = dv;
        }
        // row step: u <- 1/(W~ v)
        applyW8(v, F, Fi, o, sA0, sB0, lane, warp);
        #pragma unroll
        for (int e = 0; e < EPB; e++) u[e] = __fdividef(1.0f, o[e]);
        // uniform convergence decision (sdev writes fenced by row-step bar)
        float dmax = 0.f;
        #pragma unroll
        for (int q = 0; q < LWARPS; q++) dmax = fmaxf(dmax, sdev[par][q]);
        if (dmax < TOLC) break;   // matrix converged; ref freezes from here
    }

    // ---- Final: dcg = sum_k u_k * (W~ (v .* labs))_k / disc_k  (buffer 1) --
    {
        #pragma unroll
        for (int e = 0; e < EPB; e++) x[e] = v[e] * L[e];
        applyW8(x, F, Fi, o, sA1, sB1, lane, warp);
        float d = 0.f;
        #pragma unroll
        for (int e = 0; e < EPB; e++)
            d += u[e] * o[e] / log2f((float)(base + e) + 2.0f);
        d = warp_sum(d);
        if (lane == 0) sred[warp] = d;
        __syncthreads();
        if (warp == 0 && lane == 0) {
            float q = 0.f;
            #pragma unroll
            for (int i = 0; i < LWARPS; i++) q += sred[i];
            out[0] = 1.0f - q / s_idcg;
        }
    }
}

extern "C" void kernel_launch(void* const* d_in, const int* in_sizes, int n_in,
                              void* d_out, int out_size) {
    const float* y_pred = (const float*)d_in[0];
    const float* y_true = (const float*)d_in[1];
    float* out = (float*)d_out;
    (void)in_sizes; (void)n_in; (void)out_size;
    softndcg_kernel<<<NBLK, NTHR>>>(y_pred, y_true, out);
}